// round 3
// baseline (speedup 1.0000x reference)
#include <cuda_runtime.h>
#include <math.h>

#define BB   16
#define NN   4096
#define KK   4096
#define NCHUNK 4
#define CHUNK  1024      // NN / NCHUNK
#define IN1  16384       // KK + 3*KK
#define H1   1024
#define H2   512
#define OUTD 256

typedef unsigned long long ull;

// packed f32x2 helpers (sm_103a)
#define FMA2(out, a, b, c) asm("fma.rn.f32x2 %0, %1, %2, %3;" : "=l"(out) : "l"(a), "l"(b), "l"(c))
#define MUL2(out, a, b)    asm("mul.rn.f32x2 %0, %1, %2;"     : "=l"(out) : "l"(a), "l"(b))
#define ADD2(out, a, b)    asm("add.rn.f32x2 %0, %1, %2;"     : "=l"(out) : "l"(a), "l"(b))

__device__ __forceinline__ ull pk2(float lo, float hi) {
    ull r; asm("mov.b64 %0, {%1, %2};" : "=l"(r) : "f"(lo), "f"(hi)); return r;
}
__device__ __forceinline__ void upk2(float& lo, float& hi, ull v) {
    asm("mov.b64 {%0, %1}, %2;" : "=f"(lo), "=f"(hi) : "l"(v));
}

// ---- scratch (no allocations allowed) ----
__device__ float g_best[BB * KK * NCHUNK];
__device__ int   g_bidx[BB * KK * NCHUNK];
__device__ float g_part1[32 * BB * H1];             // 2 MB
__device__ float g_h1[BB * H1];
__device__ float g_part2[16 * BB * H2];
__device__ float g_h2[BB * H2];
__device__ float g_part3[16 * BB * OUTD];

// ============================================================
// Kernel 1: partial argmin over an N-chunk, bit-matching reference
// fp32 arithmetic, 2 points per packed f32x2 op.
// smem holds (-2x,-2y,-2z,pn) pairs:
//   spA[i] = {-2x(2i), -2x(2i+1), -2y(2i), -2y(2i+1)}
//   spB[i] = {-2z(2i), -2z(2i+1),  pn(2i),  pn(2i+1)}
// c3 = fma(bz,-2z, fma(by,-2y, rn(bx*-2x))) == -2*cr exactly,
// d  = rn(c3 + t) == fma(-2, cr, t)  (bit-identical to reference)
// grid: (KK/256, NCHUNK, BB), block: 256
// ============================================================
__global__ void k_argmin(const float* __restrict__ pc,
                         const float* __restrict__ basis) {
    __shared__ __align__(16) ulonglong2 spA[CHUNK / 2];
    __shared__ __align__(16) ulonglong2 spB[CHUNK / 2];
    const int b  = blockIdx.z;
    const int c  = blockIdx.y;
    const int n0 = c * CHUNK;

    const float* pcb = pc + ((size_t)b * NN + n0) * 3;
    for (int i = threadIdx.x; i < CHUNK / 2; i += blockDim.x) {
        float x0 = pcb[6 * i + 0], y0 = pcb[6 * i + 1], z0 = pcb[6 * i + 2];
        float x1 = pcb[6 * i + 3], y1 = pcb[6 * i + 4], z1 = pcb[6 * i + 5];
        float pn0 = __fadd_rn(__fadd_rn(__fmul_rn(x0, x0), __fmul_rn(y0, y0)),
                              __fmul_rn(z0, z0));
        float pn1 = __fadd_rn(__fadd_rn(__fmul_rn(x1, x1), __fmul_rn(y1, y1)),
                              __fmul_rn(z1, z1));
        ((float4*)spA)[i] = make_float4(-2.0f * x0, -2.0f * x1, -2.0f * y0, -2.0f * y1);
        ((float4*)spB)[i] = make_float4(-2.0f * z0, -2.0f * z1, pn0, pn1);
    }
    __syncthreads();

    const int k = blockIdx.x * blockDim.x + threadIdx.x;
    const float bx = basis[k * 3 + 0];
    const float by = basis[k * 3 + 1];
    const float bz = basis[k * 3 + 2];
    const float bn = __fadd_rn(__fadd_rn(__fmul_rn(bx, bx), __fmul_rn(by, by)),
                               __fmul_rn(bz, bz));
    const ull bxp = pk2(bx, bx);
    const ull byp = pk2(by, by);
    const ull bzp = pk2(bz, bz);
    const ull bnp = pk2(bn, bn);

    float best = 3.0e38f;
    int   bi   = 0;
    #pragma unroll 8
    for (int i = 0; i < CHUNK / 2; i++) {
        ulonglong2 qa = spA[i];          // .x = x-pair, .y = y-pair
        ulonglong2 qb = spB[i];          // .x = z-pair, .y = pn-pair
        ull cr, t, d;
        MUL2(cr, bxp, qa.x);
        FMA2(cr, byp, qa.y, cr);
        FMA2(cr, bzp, qb.x, cr);
        ADD2(t, bnp, qb.y);
        ADD2(d, cr, t);
        float d0, d1;
        upk2(d0, d1, d);
        float pm = fminf(d0, d1);
        if (pm < best) {                 // strict < => earlier n wins between pairs
            bi   = (d0 <= d1) ? (2 * i) : (2 * i + 1);   // tie within pair -> even n
            best = pm;
        }
    }

    const int o = (b * KK + k) * NCHUNK + c;
    g_best[o] = best;
    g_bidx[o] = n0 + bi;
}

// ============================================================
// Kernel 2: combine chunk partials (ascending chunk order, strict <),
// gather nearest point, write bps row: [dists(4096) | deltas(4096*3)]
// ============================================================
__global__ void k_finish(const float* __restrict__ pc,
                         const float* __restrict__ basis,
                         float* __restrict__ out_bps) {
    const int t = blockIdx.x * blockDim.x + threadIdx.x;
    if (t >= BB * KK) return;
    const int b = t >> 12;
    const int k = t & (KK - 1);

    float best = g_best[t * NCHUNK];
    int   bi   = g_bidx[t * NCHUNK];
    #pragma unroll
    for (int c = 1; c < NCHUNK; c++) {
        float v = g_best[t * NCHUNK + c];
        int   i = g_bidx[t * NCHUNK + c];
        if (v < best) { best = v; bi = i; }
    }

    const float* p = pc + ((size_t)b * NN + bi) * 3;
    const float dx = __fadd_rn(p[0], -basis[k * 3 + 0]);
    const float dy = __fadd_rn(p[1], -basis[k * 3 + 1]);
    const float dz = __fadd_rn(p[2], -basis[k * 3 + 2]);
    const float ss = __fadd_rn(__fadd_rn(__fmul_rn(dx, dx), __fmul_rn(dy, dy)),
                               __fmul_rn(dz, dz));
    const float dist = sqrtf(ss);

    float* row = out_bps + (size_t)b * IN1;
    row[k]              = dist;
    row[KK + 3 * k + 0] = dx;
    row[KK + 3 * k + 1] = dy;
    row[KK + 3 * k + 2] = dz;
}

// ============================================================
// Split-K GEMM (f32x2): part[ic][m][j] = sum_{i in chunk} A[m][i]*W[i][j]
// acc held as 8 packed m-pairs. grid: (H/256, INsz/CI), block 256.
// ============================================================
template <int CI>
__global__ void k_gemm(const float* __restrict__ A,
                       const float* __restrict__ W,
                       float* __restrict__ part,
                       int INsz, int H) {
    __shared__ __align__(16) float sA[CI * 16];
    const int i0 = blockIdx.y * CI;

    for (int idx = threadIdx.x; idx < CI * 16; idx += 256) {
        const int m  = idx / CI;
        const int il = idx % CI;
        sA[il * 16 + m] = A[(size_t)m * INsz + i0 + il];
    }
    __syncthreads();

    const int j = blockIdx.x * 256 + threadIdx.x;
    ull acc[8];
    #pragma unroll
    for (int m = 0; m < 8; m++) acc[m] = 0ull;

    const float* wp = W + (size_t)i0 * H + j;
    #pragma unroll 4
    for (int il = 0; il < CI; il++) {
        const float w = *wp;
        wp += H;
        const ull wpk = pk2(w, w);
        const ulonglong2* ap = (const ulonglong2*)(sA + il * 16);
        ulonglong2 a0 = ap[0], a1 = ap[1], a2 = ap[2], a3 = ap[3];
        FMA2(acc[0], a0.x, wpk, acc[0]);
        FMA2(acc[1], a0.y, wpk, acc[1]);
        FMA2(acc[2], a1.x, wpk, acc[2]);
        FMA2(acc[3], a1.y, wpk, acc[3]);
        FMA2(acc[4], a2.x, wpk, acc[4]);
        FMA2(acc[5], a2.y, wpk, acc[5]);
        FMA2(acc[6], a3.x, wpk, acc[6]);
        FMA2(acc[7], a3.y, wpk, acc[7]);
    }

    float* pp = part + ((size_t)blockIdx.y * 16) * H + j;
    #pragma unroll
    for (int t = 0; t < 8; t++) {
        float lo, hi;
        upk2(lo, hi, acc[t]);
        pp[(size_t)(2 * t)     * H] = lo;
        pp[(size_t)(2 * t + 1) * H] = hi;
    }
}

// ============================================================
// Fast reduce for layer 1: 32 parts over BB*H1=16384 elements.
// grid 128, block 256: 128 elements/block, 2-way part split + smem.
// ============================================================
__global__ void k_reduce_big(const float* __restrict__ part,
                             const float* __restrict__ bias,
                             float* __restrict__ outv) {
    __shared__ float sm[128];
    const int el = threadIdx.x & 127;
    const int h  = threadIdx.x >> 7;
    const int e  = blockIdx.x * 128 + el;

    const float* p = part + (size_t)h * 16 * (BB * H1) + e;
    float s = 0.0f;
    #pragma unroll
    for (int q = 0; q < 16; q++) s += p[(size_t)q * (BB * H1)];

    if (h == 1) sm[el] = s;
    __syncthreads();
    if (h == 0) {
        float v = s + sm[el];
        v += bias[e & (H1 - 1)];
        if (v < 0.0f) v *= 0.2f;
        outv[e] = v;
    }
}

// ============================================================
// Generic deterministic split-K reduce + bias (+ optional leaky relu)
// ============================================================
__global__ void k_reduce(const float* __restrict__ part,
                         const float* __restrict__ bias,
                         float* __restrict__ outv,
                         int H, int nparts, int do_lrelu) {
    const int t = blockIdx.x * blockDim.x + threadIdx.x;
    const int total = BB * H;
    if (t >= total) return;
    float s = 0.0f;
    for (int p = 0; p < nparts; p++) s += part[(size_t)p * total + t];
    s += bias[t & (H - 1)];
    if (do_lrelu && s < 0.0f) s *= 0.2f;
    outv[t] = s;
}

// ============================================================
extern "C" void kernel_launch(void* const* d_in, const int* in_sizes, int n_in,
                              void* d_out, int out_size) {
    const float* pc    = (const float*)d_in[0];
    const float* basis = (const float*)d_in[1];
    const float* W1    = (const float*)d_in[2];
    const float* b1    = (const float*)d_in[3];
    const float* W2    = (const float*)d_in[4];
    const float* b2    = (const float*)d_in[5];
    const float* W3    = (const float*)d_in[6];
    const float* b3    = (const float*)d_in[7];

    float* out = (float*)d_out;            // global_feature: [16][256]
    float* bps = out + BB * OUTD;          // bps_feature:    [16][16384]

    float *p1, *p2, *p3, *h1, *h2;
    cudaGetSymbolAddress((void**)&p1, g_part1);
    cudaGetSymbolAddress((void**)&p2, g_part2);
    cudaGetSymbolAddress((void**)&p3, g_part3);
    cudaGetSymbolAddress((void**)&h1, g_h1);
    cudaGetSymbolAddress((void**)&h2, g_h2);

    k_argmin<<<dim3(KK / 256, NCHUNK, BB), 256>>>(pc, basis);
    k_finish<<<(BB * KK) / 256, 256>>>(pc, basis, bps);

    k_gemm<512><<<dim3(H1 / 256, IN1 / 512), 256>>>(bps, W1, p1, IN1, H1);
    k_reduce_big<<<128, 256>>>(p1, b1, h1);

    k_gemm<64><<<dim3(H2 / 256, H1 / 64), 256>>>(h1, W2, p2, H1, H2);
    k_reduce<<<(BB * H2) / 256, 256>>>(p2, b2, h2, H2, 16, 1);

    k_gemm<32><<<dim3(OUTD / 256, H2 / 32), 256>>>(h2, W3, p3, H2, OUTD);
    k_reduce<<<(BB * OUTD) / 256, 256>>>(p3, b3, out, OUTD, 16, 0);
}